// round 15
// baseline (speedup 1.0000x reference)
#include <cuda_runtime.h>
#include <cstdint>
#include <math_constants.h>

#define LOG2E 1.4426950408889634f

typedef unsigned long long u64;

// Scratch: 16 m-chunks x (8*4096) n's: locally-shifted partial sums + local max.
__device__ float g_partE[16 * 32768];
__device__ float g_partT[16 * 32768];
__device__ float g_partM[16 * 32768];

__device__ __forceinline__ u64 f2fma(u64 a, u64 b, u64 c) {
    u64 r; asm("fma.rn.f32x2 %0,%1,%2,%3;" : "=l"(r) : "l"(a), "l"(b), "l"(c)); return r;
}
__device__ __forceinline__ u64 f2add(u64 a, u64 b) {
    u64 r; asm("add.rn.f32x2 %0,%1,%2;" : "=l"(r) : "l"(a), "l"(b)); return r;
}
__device__ __forceinline__ u64 f2mul(u64 a, u64 b) {
    u64 r; asm("mul.rn.f32x2 %0,%1,%2;" : "=l"(r) : "l"(a), "l"(b)); return r;
}
__device__ __forceinline__ u64 pk(float lo, float hi) {
    u64 r; asm("mov.b64 %0,{%1,%2};" : "=l"(r) : "f"(lo), "f"(hi)); return r;
}
__device__ __forceinline__ void up(u64 v, float& lo, float& hi) {
    asm("mov.b64 {%0,%1},%2;" : "=f"(lo), "=f"(hi) : "l"(v));
}
__device__ __forceinline__ float ex2f(float x) {
    float r; asm("ex2.approx.f32 %0,%1;" : "=f"(r) : "f"(x)); return r;
}

// B=8, N=4096, M=4096, D=3 hardcoded.
// Grid: 1024 blocks = 8 batches x 8 n-chunks x 16 m-chunks.
// Block: 256 threads; each thread owns 2 n's; block owns 256 m's. 8-m tiles.
// Lagged-shift online softmax: accumulate 2^(g-S); S raised only on a rare
// warp-uniform vote (tile max exceeding S+60). True max M tracked on ALU pipe.
__global__ void __launch_bounds__(256, 3) fape_fused_kernel(
    const float* __restrict__ Xp,   // (8,4096,3)
    const float* __restrict__ Xt,   // (8,4096,3)
    const float* __restrict__ Rp,   // (8,3,3)
    const float* __restrict__ tp,   // (8,3)
    const float* __restrict__ Rt,   // (8,3,3)
    const float* __restrict__ tt,   // (8,3)
    const float* __restrict__ temp, // (1,)
    float* __restrict__ out)
{
    // 128 m-pair groups x 4 packed u64: [vx01, vy01, vz01, vw01].
    __shared__ __align__(16) u64 sm[128 * 4];   // 4 KB

    const int mchunk = blockIdx.x & 15;
    const int nchunk = (blockIdx.x >> 4) & 7;
    const int b      = blockIdx.x >> 7;
    const int tid    = threadIdx.x;

    if (blockIdx.x == 0 && tid == 0) *out = 0.0f;   // reduce kernel accumulates

    const float T = *temp;
    const float s = -LOG2E / T;   // logit scale in log2 domain (s < 0)

    // ---- Fill smem: v = (s*-2*Xt', s*|Xt'|^2) for this block's 256 m's ----
    {
        const float* R  = Rt + b * 9;
        const float* tv = tt + b * 3;
        const float r00 = R[0], r01 = R[1], r02 = R[2];
        const float r10 = R[3], r11 = R[4], r12 = R[5];
        const float r20 = R[6], r21 = R[7], r22 = R[8];
        const float tx = tv[0], ty = tv[1], tz = tv[2];
        const float s2 = s * -2.0f;

        const float* xm = Xt + (size_t)(b * 4096 + mchunk * 256 + tid) * 3;
        const float x = xm[0], y = xm[1], z = xm[2];
        const float ax = r00 * x + r01 * y + r02 * z + tx;
        const float ay = r10 * x + r11 * y + r12 * z + ty;
        const float az = r20 * x + r21 * y + r22 * z + tz;
        const float sq = ax * ax + ay * ay + az * az;
        const int j = tid >> 1, h = tid & 1;
        float* w = (float*)(sm + j * 4);
        w[0 + h] = s2 * ax;   // vx
        w[2 + h] = s2 * ay;   // vy
        w[4 + h] = s2 * az;   // vz
        w[6 + h] = s * sq;    // vw
    }

    // ---- Per-thread: two n's ----
    const float* Rq = Rp + b * 9;
    const float* tq = tp + b * 3;
    const float q00 = Rq[0], q01 = Rq[1], q02 = Rq[2];
    const float q10 = Rq[3], q11 = Rq[4], q12 = Rq[5];
    const float q20 = Rq[6], q21 = Rq[7], q22 = Rq[8];
    const float u0 = tq[0], u1 = tq[1], u2 = tq[2];

    const int n0 = nchunk * 512 + tid;   // and n1 = n0 + 256
    u64 PX[2], PY[2], PZ[2];
    float SC[2];
    #pragma unroll
    for (int i = 0; i < 2; i++) {
        const float* xa = Xp + (size_t)(b * 4096 + n0 + i * 256) * 3;
        const float ax = xa[0], ay = xa[1], az = xa[2];
        const float px = q00 * ax + q01 * ay + q02 * az + u0;
        const float py = q10 * ax + q11 * ay + q12 * az + u1;
        const float pz = q20 * ax + q21 * ay + q22 * az + u2;
        SC[i] = s * (px * px + py * py + pz * pz);
        PX[i] = pk(px, px);
        PY[i] = pk(py, py);
        PZ[i] = pk(pz, pz);
    }

    // Per-chain state. NS = packed(-Sh); thr = Sh + 60 (updated on rescale only).
    float Mx[2]  = { -1e30f, -1e30f };
    float Sh[2]  = { -1e30f, -1e30f };
    float thr[2] = { -1e30f + 60.0f, -1e30f + 60.0f };
    u64 NS[2] = { pk(1e30f, 1e30f), pk(1e30f, 1e30f) };
    u64 SE[2] = { 0ull, 0ull };
    u64 SG[2] = { 0ull, 0ull };

    __syncthreads();

    // 32 tiles x (4 groups = 8 m's); v loaded once per group, feeds 2 chains.
    for (int t = 0; t < 32; t++) {
        const u64* base = sm + t * 16;

        u64 g[2][4];   // [chain][group]
        #pragma unroll
        for (int k = 0; k < 4; k++) {
            const ulonglong2 v1 = *(const ulonglong2*)(base + k * 4);     // vx, vy
            const ulonglong2 v2 = *(const ulonglong2*)(base + k * 4 + 2); // vz, vw
            #pragma unroll
            for (int i = 0; i < 2; i++) {
                u64 a = f2fma(PZ[i], v2.x, v2.y);
                a = f2fma(PY[i], v1.y, a);
                g[i][k] = f2fma(PX[i], v1.x, a);
            }
        }

        // Tile maxes (ALU pipe, off the accumulate critical path).
        bool need = false;
        #pragma unroll
        for (int i = 0; i < 2; i++) {
            float m4[4];
            #pragma unroll
            for (int k = 0; k < 4; k++) { float lo, hi; up(g[i][k], lo, hi); m4[k] = fmaxf(lo, hi); }
            const float tm = fmaxf(fmaxf(m4[0], m4[1]), fmaxf(m4[2], m4[3]));
            Mx[i] = fmaxf(Mx[i], tm);
            need |= (tm > thr[i]);
        }

        // Rare warp-uniform rescale: bring shift up to the true max.
        if (__any_sync(0xffffffffu, need)) {
            #pragma unroll
            for (int i = 0; i < 2; i++) {
                const float ds = Sh[i] - Mx[i];      // <= 0, finite
                const float w  = ex2f(ds);
                const u64 D = pk(ds, ds), W = pk(w, w);
                SG[i] = f2mul(f2fma(D, SE[i], SG[i]), W);   // (Sg + ds*Se) * w
                SE[i] = f2mul(SE[i], W);
                Sh[i]  = Mx[i];
                thr[i] = Mx[i] + 60.0f;
                NS[i]  = pk(-Mx[i], -Mx[i]);
            }
        }

        // Exp-accumulate against the (lagged) shift. Terms bounded by 2^60.
        #pragma unroll
        for (int i = 0; i < 2; i++) {
            const u64 ns = NS[i];
            u64 se = SE[i], sg = SG[i];
            #pragma unroll
            for (int k = 0; k < 4; k++) {
                const u64 dd = f2add(g[i][k], ns);
                float a0, c0; up(dd, a0, c0);
                const u64 E = pk(ex2f(a0), ex2f(c0));
                se = f2add(se, E);
                sg = f2fma(E, dd, sg);
            }
            SE[i] = se;
            SG[i] = sg;
        }
    }

    // Writeback: rescale Sh -> Mx so partials are (E, T, M).
    #pragma unroll
    for (int i = 0; i < 2; i++) {
        float e0, e1, t0, t1;
        up(SE[i], e0, e1);
        up(SG[i], t0, t1);
        const float eS = e0 + e1;
        const float tS = t0 + t1;
        const float ds = Sh[i] - Mx[i];              // <= 0
        const float w  = ex2f(ds);
        const int gi = mchunk * 32768 + b * 4096 + n0 + i * 256;
        g_partE[gi] = eS * w;
        g_partT[gi] = (tS + ds * eS) * w;
        g_partM[gi] = SC[i] + Mx[i];
    }
}

// Exact combine: each thread owns 4 consecutive n's; all loads are coalesced
// float4 from the [chunk][n] planes (L2-resident). Grid 32 x 256.
__global__ void __launch_bounds__(256) fape_reduce_kernel(
    const float* __restrict__ temp, float* __restrict__ out)
{
    const int gidx = blockIdx.x * 256 + threadIdx.x;   // 0..8191
    const float4* PM = (const float4*)g_partM;
    const float4* PE = (const float4*)g_partE;
    const float4* PT = (const float4*)g_partT;

    // Pass 1: all 16 chunk maxes for the 4 n's (64 independent loads).
    float4 Mv[16];
    #pragma unroll
    for (int c = 0; c < 16; c++)
        Mv[c] = PM[c * 8192 + gidx];

    float M0 = Mv[0].x, M1 = Mv[0].y, M2 = Mv[0].z, M3 = Mv[0].w;
    #pragma unroll
    for (int c = 1; c < 16; c++) {
        M0 = fmaxf(M0, Mv[c].x);
        M1 = fmaxf(M1, Mv[c].y);
        M2 = fmaxf(M2, Mv[c].z);
        M3 = fmaxf(M3, Mv[c].w);
    }

    // Pass 2: weighted combine.
    float E0 = 0, E1 = 0, E2 = 0, E3 = 0;
    float T0 = 0, T1 = 0, T2 = 0, T3 = 0;
    #pragma unroll
    for (int c = 0; c < 16; c++) {
        const float4 Ev = PE[c * 8192 + gidx];
        const float4 Tv = PT[c * 8192 + gidx];
        float dm, w;
        dm = Mv[c].x - M0; w = ex2f(dm);
        E0 = fmaf(w, Ev.x, E0); T0 = fmaf(w, fmaf(dm, Ev.x, Tv.x), T0);
        dm = Mv[c].y - M1; w = ex2f(dm);
        E1 = fmaf(w, Ev.y, E1); T1 = fmaf(w, fmaf(dm, Ev.y, Tv.y), T1);
        dm = Mv[c].z - M2; w = ex2f(dm);
        E2 = fmaf(w, Ev.z, E2); T2 = fmaf(w, fmaf(dm, Ev.z, Tv.z), T2);
        dm = Mv[c].w - M3; w = ex2f(dm);
        E3 = fmaf(w, Ev.w, E3); T3 = fmaf(w, fmaf(dm, Ev.w, Tv.w), T3);
    }

    const float invs = -(*temp) / LOG2E;   // 1/s
    // E >= 1 per n (the argmax chunk contributes its max term = 1).
    const float wsum = (T0 / E0 + M0) + (T1 / E1 + M1)
                     + (T2 / E2 + M2) + (T3 / E3 + M3);
    const float weighted = invs * wsum * (1.0f / (8.0f * 4096.0f));

    __shared__ float red[256];
    red[threadIdx.x] = weighted;
    __syncthreads();
    #pragma unroll
    for (int off = 128; off > 0; off >>= 1) {
        if (threadIdx.x < off) red[threadIdx.x] += red[threadIdx.x + off];
        __syncthreads();
    }
    if (threadIdx.x == 0)
        atomicAdd(out, red[0]);
}

extern "C" void kernel_launch(void* const* d_in, const int* in_sizes, int n_in,
                              void* d_out, int out_size) {
    const float* Xp   = (const float*)d_in[0];
    const float* Xt   = (const float*)d_in[1];
    const float* Rp   = (const float*)d_in[2];
    const float* tp   = (const float*)d_in[3];
    const float* Rt   = (const float*)d_in[4];
    const float* tt   = (const float*)d_in[5];
    const float* temp = (const float*)d_in[6];
    float* out = (float*)d_out;

    fape_fused_kernel<<<1024, 256>>>(Xp, Xt, Rp, tp, Rt, tt, temp, out);
    fape_reduce_kernel<<<32, 256>>>(temp, out);
}